// round 12
// baseline (speedup 1.0000x reference)
#include <cuda_runtime.h>
#include <math.h>

#define Npts   16384
#define PER    2048
#define Mc     4096
#define Kn     64
#define R2v    0.0625f
#define CIN    128
#define HID    256
#define COUT   256
#define CSTRIDE 4

__device__ int   g_nbr[Mc * Kn];
__device__ int   g_cnt[Mc];
__device__ float g_P[Npts * HID];   // x @ W1[0:128]          (16 MB, L2-resident)
__device__ float g_D[Mc * HID];     // x_dst @ W1[128:256]+b1 (4 MB)

// ---------------------------------------------------------------------------
// Kernel 1: ball query. One block per center. Collect in-radius candidates
// (same batch block), bitonic-sort by packed (d2|idx) key, keep 64 nearest.
// ---------------------------------------------------------------------------
__global__ void __launch_bounds__(256) ball_query_kernel(const float* __restrict__ pos)
{
    __shared__ unsigned long long s[PER];
    __shared__ int cnt;
    int m = blockIdx.x;
    int c = m * CSTRIDE;
    int base = (c / PER) * PER;

    if (threadIdx.x == 0) cnt = 0;
    __syncthreads();

    float px = pos[c * 3 + 0], py = pos[c * 3 + 1], pz = pos[c * 3 + 2];
    for (int t = threadIdx.x; t < PER; t += blockDim.x) {
        int n = base + t;
        float dx = pos[n * 3 + 0] - px;
        float dy = pos[n * 3 + 1] - py;
        float dz = pos[n * 3 + 2] - pz;
        float d2 = dx * dx + dy * dy + dz * dz;
        if (d2 <= R2v) {
            int p = atomicAdd(&cnt, 1);
            s[p] = (((unsigned long long)__float_as_uint(d2)) << 32) | (unsigned)n;
        }
    }
    __syncthreads();
    int count = cnt;

    if (count > Kn) {
        int P = Kn;
        while (P < count) P <<= 1;
        for (int t = count + threadIdx.x; t < P; t += blockDim.x) s[t] = ~0ull;
        __syncthreads();
        for (int k2 = 2; k2 <= P; k2 <<= 1) {
            for (int j = k2 >> 1; j > 0; j >>= 1) {
                for (int i = threadIdx.x; i < P; i += blockDim.x) {
                    int ix = i ^ j;
                    if (ix > i) {
                        unsigned long long a = s[i], b = s[ix];
                        bool up = ((i & k2) == 0);
                        if ((a > b) == up) { s[i] = b; s[ix] = a; }
                    }
                }
                __syncthreads();
            }
        }
    }
    int nv = count < Kn ? count : Kn;
    for (int k = threadIdx.x; k < Kn; k += blockDim.x)
        g_nbr[m * Kn + k] = (k < nv) ? (int)(unsigned)(s[k] & 0xffffffffu) : c;
    if (threadIdx.x == 0) g_cnt[m] = nv;
}

// ---------------------------------------------------------------------------
// Kernel P: out[i] = X[i*rstride] @ W (+bias). 64 rows x 256 cols per block,
// K=128. 8x8 register tile, f32x2 FMAs, B pairs loaded pre-packed as b64.
// ---------------------------------------------------------------------------
__global__ void __launch_bounds__(256) pre_gemm_kernel(
    const float* __restrict__ X, const float* __restrict__ W,
    const float* __restrict__ bias, float* __restrict__ out, int rstride)
{
    __shared__ float A[Kn * CIN];
    int r0 = blockIdx.x * 64;
    int tid = threadIdx.x;
    int ty = tid >> 5, tx = tid & 31;

    for (int k = ty; k < 64; k += 8) {
        const float4* src = (const float4*)(X + (long long)(r0 + k) * rstride * CIN);
        ((float4*)(A + k * CIN))[tx] = __ldg(src + tx);
    }
    __syncthreads();

    unsigned long long acc[32];
    #pragma unroll
    for (int i = 0; i < 32; i++) acc[i] = 0ull;

    const float* arow = A + (ty * 8) * CIN;
    #pragma unroll 4
    for (int kk = 0; kk < CIN; kk++) {
        const ulonglong2* wp = (const ulonglong2*)(W + (long long)kk * HID + tx * 8);
        ulonglong2 bA = __ldg(wp);
        ulonglong2 bB = __ldg(wp + 1);
        #pragma unroll
        for (int r = 0; r < 8; r++) {
            float a = arow[r * CIN + kk];
            unsigned long long aa;
            asm("mov.b64 %0,{%1,%1};" : "=l"(aa) : "f"(a));
            asm("fma.rn.f32x2 %0,%1,%2,%0;" : "+l"(acc[r * 4 + 0]) : "l"(aa), "l"(bA.x));
            asm("fma.rn.f32x2 %0,%1,%2,%0;" : "+l"(acc[r * 4 + 1]) : "l"(aa), "l"(bA.y));
            asm("fma.rn.f32x2 %0,%1,%2,%0;" : "+l"(acc[r * 4 + 2]) : "l"(aa), "l"(bB.x));
            asm("fma.rn.f32x2 %0,%1,%2,%0;" : "+l"(acc[r * 4 + 3]) : "l"(aa), "l"(bB.y));
        }
    }

    float bv[8];
    #pragma unroll
    for (int q = 0; q < 8; q++) bv[q] = bias ? bias[tx * 8 + q] : 0.f;
    #pragma unroll
    for (int r = 0; r < 8; r++) {
        float f[8];
        #pragma unroll
        for (int q = 0; q < 4; q++)
            asm("mov.b64 {%0,%1},%2;" : "=f"(f[q * 2]), "=f"(f[q * 2 + 1]) : "l"(acc[r * 4 + q]));
        #pragma unroll
        for (int q = 0; q < 8; q++) f[q] += bv[q];
        float* op = out + (long long)(r0 + ty * 8 + r) * HID + tx * 8;
        ((float4*)op)[0] = make_float4(f[0], f[1], f[2], f[3]);
        ((float4*)op)[1] = make_float4(f[4], f[5], f[6], f[7]);
    }
}

// ---------------------------------------------------------------------------
// Kernel 2: per-center. H[k] = relu(P[nbr_k] + D[m] + rel_loc @ W1c), then
// GEMM2 (H @ W2) with fused masked-max epilogue. 256 thr, 8x8 tile, f32x2.
// ---------------------------------------------------------------------------
__global__ void __launch_bounds__(256) edge_mlp_kernel(
    const float* __restrict__ pos, const float* __restrict__ lframes,
    const float* __restrict__ W1, const float* __restrict__ W2,
    const float* __restrict__ b2, float* __restrict__ out)
{
    extern __shared__ float smem[];
    float* H   = smem;                 // [64][256]
    float* Dsh = H + Kn * HID;         // [256]
    float* Wc  = Dsh + HID;            // [3][256]  W1 rows 256..258
    float* AUX = Wc + 3 * HID;         // pos_dst(3), lframe(9)
    float* RED = H;                    // overlay after GEMM2 reads complete

    int m = blockIdx.x;
    int c = m * CSTRIDE;
    int tid = threadIdx.x;
    int ty = tid >> 5, tx = tid & 31;

    if (tid < 64) ((float4*)Dsh)[tid] = __ldg((const float4*)(g_D + (long long)m * HID) + tid);
    if (tid < 192) ((float4*)Wc)[tid] = __ldg((const float4*)(W1 + 256 * HID) + tid);
    if (tid >= 192 && tid < 195) AUX[tid - 192] = pos[c * 3 + (tid - 192)];
    if (tid >= 195 && tid < 204) AUX[3 + tid - 195] = lframes[c * 9 + (tid - 195)];
    __syncthreads();

    int nv = g_cnt[m];

    // Gather P rows + activation
    for (int k = ty; k < Kn; k += 8) {
        int n = g_nbr[m * Kn + k];
        float rx = __ldg(pos + n * 3 + 0) - AUX[0];
        float ry = __ldg(pos + n * 3 + 1) - AUX[1];
        float rz = __ldg(pos + n * 3 + 2) - AUX[2];
        float e0 = AUX[3] * rx + AUX[4] * ry + AUX[5] * rz;
        float e1 = AUX[6] * rx + AUX[7] * ry + AUX[8] * rz;
        float e2 = AUX[9] * rx + AUX[10] * ry + AUX[11] * rz;
        const float4* pr = (const float4*)(g_P + (long long)n * HID);
        #pragma unroll
        for (int j = tx; j < 64; j += 32) {
            float4 p = __ldg(pr + j);
            float4 d = ((float4*)Dsh)[j];
            float4 w0 = ((float4*)Wc)[j];
            float4 w1 = ((float4*)(Wc + HID))[j];
            float4 w2 = ((float4*)(Wc + 2 * HID))[j];
            float4 v;
            v.x = fmaxf(p.x + d.x + e0 * w0.x + e1 * w1.x + e2 * w2.x, 0.f);
            v.y = fmaxf(p.y + d.y + e0 * w0.y + e1 * w1.y + e2 * w2.y, 0.f);
            v.z = fmaxf(p.z + d.z + e0 * w0.z + e1 * w1.z + e2 * w2.z, 0.f);
            v.w = fmaxf(p.w + d.w + e0 * w0.w + e1 * w1.w + e2 * w2.w, 0.f);
            ((float4*)(H + k * HID))[j] = v;
        }
    }
    __syncthreads();

    // GEMM2: msg = H @ W2 (b2 folded post-max)
    unsigned long long acc[32];
    #pragma unroll
    for (int i = 0; i < 32; i++) acc[i] = 0ull;
    {
        const float* hrow = H + (ty * 8) * HID;
        #pragma unroll 4
        for (int kk = 0; kk < HID; kk++) {
            const ulonglong2* wp = (const ulonglong2*)(W2 + (long long)kk * COUT + tx * 8);
            ulonglong2 bA = __ldg(wp);
            ulonglong2 bB = __ldg(wp + 1);
            #pragma unroll
            for (int r = 0; r < 8; r++) {
                float a = hrow[r * HID + kk];
                unsigned long long aa;
                asm("mov.b64 %0,{%1,%1};" : "=l"(aa) : "f"(a));
                asm("fma.rn.f32x2 %0,%1,%2,%0;" : "+l"(acc[r * 4 + 0]) : "l"(aa), "l"(bA.x));
                asm("fma.rn.f32x2 %0,%1,%2,%0;" : "+l"(acc[r * 4 + 1]) : "l"(aa), "l"(bA.y));
                asm("fma.rn.f32x2 %0,%1,%2,%0;" : "+l"(acc[r * 4 + 2]) : "l"(aa), "l"(bB.x));
                asm("fma.rn.f32x2 %0,%1,%2,%0;" : "+l"(acc[r * 4 + 3]) : "l"(aa), "l"(bB.y));
            }
        }
    }

    // Masked max over this thread's 8 rows
    float cmax[8];
    #pragma unroll
    for (int q = 0; q < 8; q++) cmax[q] = -3.402823466e38f;
    #pragma unroll
    for (int r = 0; r < 8; r++) {
        if (ty * 8 + r < nv) {
            #pragma unroll
            for (int q = 0; q < 4; q++) {
                float lo, hi;
                asm("mov.b64 {%0,%1},%2;" : "=f"(lo), "=f"(hi) : "l"(acc[r * 4 + q]));
                cmax[q * 2 + 0] = fmaxf(cmax[q * 2 + 0], lo);
                cmax[q * 2 + 1] = fmaxf(cmax[q * 2 + 1], hi);
            }
        }
    }
    __syncthreads();   // all H reads done before overlay
    ((float4*)(RED + ty * 256 + tx * 8))[0] = make_float4(cmax[0], cmax[1], cmax[2], cmax[3]);
    ((float4*)(RED + ty * 256 + tx * 8))[1] = make_float4(cmax[4], cmax[5], cmax[6], cmax[7]);
    __syncthreads();
    {
        int col = tid;
        float v = RED[col];
        #pragma unroll
        for (int t = 1; t < 8; t++) v = fmaxf(v, RED[t * 256 + col]);
        out[(long long)m * COUT + col] = v + b2[col];   // nv >= 1 (center itself)
    }
}

// ---------------------------------------------------------------------------
// Kernel 3: auxiliary tuple outputs (pos_dst, batch_dst, lframes_dst)
// ---------------------------------------------------------------------------
__global__ void extras_kernel(const float* __restrict__ pos, const int* __restrict__ batch,
                              const float* __restrict__ lframes, float* __restrict__ out)
{
    int m = blockIdx.x * blockDim.x + threadIdx.x;
    if (m >= Mc) return;
    int c = m * CSTRIDE;
    long long o = (long long)Mc * COUT;
    out[o + m * 3 + 0] = pos[c * 3 + 0];
    out[o + m * 3 + 1] = pos[c * 3 + 1];
    out[o + m * 3 + 2] = pos[c * 3 + 2];
    o += (long long)Mc * 3;
    out[o + m] = (float)batch[c];
    o += Mc;
    #pragma unroll
    for (int j = 0; j < 9; j++) out[o + m * 9 + j] = lframes[c * 9 + j];
}

// ---------------------------------------------------------------------------
extern "C" void kernel_launch(void* const* d_in, const int* in_sizes, int n_in,
                              void* d_out, int out_size)
{
    const float* x       = (const float*)d_in[0];
    const float* pos     = (const float*)d_in[1];
    const int*   batch   = (const int*)  d_in[2];
    const float* lframes = (const float*)d_in[3];
    const float* W1      = (const float*)d_in[4];
    const float* b1      = (const float*)d_in[5];
    const float* W2      = (const float*)d_in[6];
    const float* b2      = (const float*)d_in[7];
    float* out = (float*)d_out;

    float* P_buf; cudaGetSymbolAddress((void**)&P_buf, g_P);
    float* D_buf; cudaGetSymbolAddress((void**)&D_buf, g_D);

    int smem_bytes = (Kn * HID + HID + 3 * HID + 16) * (int)sizeof(float);
    cudaFuncSetAttribute(edge_mlp_kernel,
                         cudaFuncAttributeMaxDynamicSharedMemorySize, smem_bytes);

    ball_query_kernel<<<Mc, 256>>>(pos);
    pre_gemm_kernel<<<Npts / 64, 256>>>(x, W1, nullptr, P_buf, 1);           // P = x @ W1a
    pre_gemm_kernel<<<Mc / 64, 256>>>(x, W1 + CIN * HID, b1, D_buf, CSTRIDE); // D = x_dst @ W1b + b1
    edge_mlp_kernel<<<Mc, 256, smem_bytes>>>(pos, lframes, W1, W2, b2, out);

    long long full = (long long)Mc * COUT + (long long)Mc * 13;
    if ((long long)out_size >= full)
        extras_kernel<<<(Mc + 255) / 256, 256>>>(pos, batch, lframes, out);
}

// round 13
// speedup vs baseline: 1.0004x; 1.0004x over previous
#include <cuda_runtime.h>
#include <math.h>

#define Npts   16384
#define PER    2048
#define Mc     4096
#define Kn     64
#define R2v    0.0625f
#define CIN    128
#define HID    256
#define COUT   256
#define CSTRIDE 4

__device__ int   g_nbr[Mc * Kn];
__device__ int   g_cnt[Mc];
__device__ float g_P[Npts * HID];   // x @ W1[0:128]          (16 MB, L2-resident)
__device__ float g_D[Mc * HID];     // x_dst @ W1[128:256]+b1 (4 MB)

// ---------------------------------------------------------------------------
// Kernel 1: ball query. One block per center. Collect in-radius candidates
// (same batch block), bitonic-sort by packed (d2|idx) key, keep 64 nearest.
// ---------------------------------------------------------------------------
__global__ void __launch_bounds__(256) ball_query_kernel(const float* __restrict__ pos)
{
    __shared__ unsigned long long s[PER];
    __shared__ int cnt;
    int m = blockIdx.x;
    int c = m * CSTRIDE;
    int base = (c / PER) * PER;

    if (threadIdx.x == 0) cnt = 0;
    __syncthreads();

    float px = pos[c * 3 + 0], py = pos[c * 3 + 1], pz = pos[c * 3 + 2];
    for (int t = threadIdx.x; t < PER; t += blockDim.x) {
        int n = base + t;
        float dx = pos[n * 3 + 0] - px;
        float dy = pos[n * 3 + 1] - py;
        float dz = pos[n * 3 + 2] - pz;
        float d2 = dx * dx + dy * dy + dz * dz;
        if (d2 <= R2v) {
            int p = atomicAdd(&cnt, 1);
            s[p] = (((unsigned long long)__float_as_uint(d2)) << 32) | (unsigned)n;
        }
    }
    __syncthreads();
    int count = cnt;

    if (count > Kn) {
        int P = Kn;
        while (P < count) P <<= 1;
        for (int t = count + threadIdx.x; t < P; t += blockDim.x) s[t] = ~0ull;
        __syncthreads();
        for (int k2 = 2; k2 <= P; k2 <<= 1) {
            for (int j = k2 >> 1; j > 0; j >>= 1) {
                for (int i = threadIdx.x; i < P; i += blockDim.x) {
                    int ix = i ^ j;
                    if (ix > i) {
                        unsigned long long a = s[i], b = s[ix];
                        bool up = ((i & k2) == 0);
                        if ((a > b) == up) { s[i] = b; s[ix] = a; }
                    }
                }
                __syncthreads();
            }
        }
    }
    int nv = count < Kn ? count : Kn;
    for (int k = threadIdx.x; k < Kn; k += blockDim.x)
        g_nbr[m * Kn + k] = (k < nv) ? (int)(unsigned)(s[k] & 0xffffffffu) : c;
    if (threadIdx.x == 0) g_cnt[m] = nv;
}

// ---------------------------------------------------------------------------
// Kernel P: out[i] = X[i*rstride] @ W (+bias). 64 rows x 256 cols per block,
// K=128. 8x8 register tile, f32x2 FMAs, B pairs loaded pre-packed as b64.
// ---------------------------------------------------------------------------
__global__ void __launch_bounds__(256) pre_gemm_kernel(
    const float* __restrict__ X, const float* __restrict__ W,
    const float* __restrict__ bias, float* __restrict__ out, int rstride)
{
    __shared__ float A[Kn * CIN];
    int r0 = blockIdx.x * 64;
    int tid = threadIdx.x;
    int ty = tid >> 5, tx = tid & 31;

    for (int k = ty; k < 64; k += 8) {
        const float4* src = (const float4*)(X + (long long)(r0 + k) * rstride * CIN);
        ((float4*)(A + k * CIN))[tx] = __ldg(src + tx);
    }
    __syncthreads();

    unsigned long long acc[32];
    #pragma unroll
    for (int i = 0; i < 32; i++) acc[i] = 0ull;

    const float* arow = A + (ty * 8) * CIN;
    #pragma unroll 4
    for (int kk = 0; kk < CIN; kk++) {
        const ulonglong2* wp = (const ulonglong2*)(W + (long long)kk * HID + tx * 8);
        ulonglong2 bA = __ldg(wp);
        ulonglong2 bB = __ldg(wp + 1);
        #pragma unroll
        for (int r = 0; r < 8; r++) {
            float a = arow[r * CIN + kk];
            unsigned long long aa;
            asm("mov.b64 %0,{%1,%1};" : "=l"(aa) : "f"(a));
            asm("fma.rn.f32x2 %0,%1,%2,%0;" : "+l"(acc[r * 4 + 0]) : "l"(aa), "l"(bA.x));
            asm("fma.rn.f32x2 %0,%1,%2,%0;" : "+l"(acc[r * 4 + 1]) : "l"(aa), "l"(bA.y));
            asm("fma.rn.f32x2 %0,%1,%2,%0;" : "+l"(acc[r * 4 + 2]) : "l"(aa), "l"(bB.x));
            asm("fma.rn.f32x2 %0,%1,%2,%0;" : "+l"(acc[r * 4 + 3]) : "l"(aa), "l"(bB.y));
        }
    }

    float bv[8];
    #pragma unroll
    for (int q = 0; q < 8; q++) bv[q] = bias ? bias[tx * 8 + q] : 0.f;
    #pragma unroll
    for (int r = 0; r < 8; r++) {
        float f[8];
        #pragma unroll
        for (int q = 0; q < 4; q++)
            asm("mov.b64 {%0,%1},%2;" : "=f"(f[q * 2]), "=f"(f[q * 2 + 1]) : "l"(acc[r * 4 + q]));
        #pragma unroll
        for (int q = 0; q < 8; q++) f[q] += bv[q];
        float* op = out + (long long)(r0 + ty * 8 + r) * HID + tx * 8;
        ((float4*)op)[0] = make_float4(f[0], f[1], f[2], f[3]);
        ((float4*)op)[1] = make_float4(f[4], f[5], f[6], f[7]);
    }
}

// ---------------------------------------------------------------------------
// Kernel 2: per-center. H[k] = relu(P[nbr_k] + D[m] + rel_loc @ W1c), then
// GEMM2 (H @ W2) with fused masked-max epilogue. 256 thr, 8x8 tile, f32x2.
// ---------------------------------------------------------------------------
__global__ void __launch_bounds__(256) edge_mlp_kernel(
    const float* __restrict__ pos, const float* __restrict__ lframes,
    const float* __restrict__ W1, const float* __restrict__ W2,
    const float* __restrict__ b2, float* __restrict__ out)
{
    extern __shared__ float smem[];
    float* H   = smem;                 // [64][256]
    float* Dsh = H + Kn * HID;         // [256]
    float* Wc  = Dsh + HID;            // [3][256]  W1 rows 256..258
    float* AUX = Wc + 3 * HID;         // pos_dst(3), lframe(9)
    float* RED = H;                    // overlay after GEMM2 reads complete

    int m = blockIdx.x;
    int c = m * CSTRIDE;
    int tid = threadIdx.x;
    int ty = tid >> 5, tx = tid & 31;

    if (tid < 64) ((float4*)Dsh)[tid] = __ldg((const float4*)(g_D + (long long)m * HID) + tid);
    if (tid < 192) ((float4*)Wc)[tid] = __ldg((const float4*)(W1 + 256 * HID) + tid);
    if (tid >= 192 && tid < 195) AUX[tid - 192] = pos[c * 3 + (tid - 192)];
    if (tid >= 195 && tid < 204) AUX[3 + tid - 195] = lframes[c * 9 + (tid - 195)];
    __syncthreads();

    int nv = g_cnt[m];

    // Gather P rows + activation
    for (int k = ty; k < Kn; k += 8) {
        int n = g_nbr[m * Kn + k];
        float rx = __ldg(pos + n * 3 + 0) - AUX[0];
        float ry = __ldg(pos + n * 3 + 1) - AUX[1];
        float rz = __ldg(pos + n * 3 + 2) - AUX[2];
        float e0 = AUX[3] * rx + AUX[4] * ry + AUX[5] * rz;
        float e1 = AUX[6] * rx + AUX[7] * ry + AUX[8] * rz;
        float e2 = AUX[9] * rx + AUX[10] * ry + AUX[11] * rz;
        const float4* pr = (const float4*)(g_P + (long long)n * HID);
        #pragma unroll
        for (int j = tx; j < 64; j += 32) {
            float4 p = __ldg(pr + j);
            float4 d = ((float4*)Dsh)[j];
            float4 w0 = ((float4*)Wc)[j];
            float4 w1 = ((float4*)(Wc + HID))[j];
            float4 w2 = ((float4*)(Wc + 2 * HID))[j];
            float4 v;
            v.x = fmaxf(p.x + d.x + e0 * w0.x + e1 * w1.x + e2 * w2.x, 0.f);
            v.y = fmaxf(p.y + d.y + e0 * w0.y + e1 * w1.y + e2 * w2.y, 0.f);
            v.z = fmaxf(p.z + d.z + e0 * w0.z + e1 * w1.z + e2 * w2.z, 0.f);
            v.w = fmaxf(p.w + d.w + e0 * w0.w + e1 * w1.w + e2 * w2.w, 0.f);
            ((float4*)(H + k * HID))[j] = v;
        }
    }
    __syncthreads();

    // GEMM2: msg = H @ W2 (b2 folded post-max)
    unsigned long long acc[32];
    #pragma unroll
    for (int i = 0; i < 32; i++) acc[i] = 0ull;
    {
        const float* hrow = H + (ty * 8) * HID;
        #pragma unroll 4
        for (int kk = 0; kk < HID; kk++) {
            const ulonglong2* wp = (const ulonglong2*)(W2 + (long long)kk * COUT + tx * 8);
            ulonglong2 bA = __ldg(wp);
            ulonglong2 bB = __ldg(wp + 1);
            #pragma unroll
            for (int r = 0; r < 8; r++) {
                float a = hrow[r * HID + kk];
                unsigned long long aa;
                asm("mov.b64 %0,{%1,%1};" : "=l"(aa) : "f"(a));
                asm("fma.rn.f32x2 %0,%1,%2,%0;" : "+l"(acc[r * 4 + 0]) : "l"(aa), "l"(bA.x));
                asm("fma.rn.f32x2 %0,%1,%2,%0;" : "+l"(acc[r * 4 + 1]) : "l"(aa), "l"(bA.y));
                asm("fma.rn.f32x2 %0,%1,%2,%0;" : "+l"(acc[r * 4 + 2]) : "l"(aa), "l"(bB.x));
                asm("fma.rn.f32x2 %0,%1,%2,%0;" : "+l"(acc[r * 4 + 3]) : "l"(aa), "l"(bB.y));
            }
        }
    }

    // Masked max over this thread's 8 rows
    float cmax[8];
    #pragma unroll
    for (int q = 0; q < 8; q++) cmax[q] = -3.402823466e38f;
    #pragma unroll
    for (int r = 0; r < 8; r++) {
        if (ty * 8 + r < nv) {
            #pragma unroll
            for (int q = 0; q < 4; q++) {
                float lo, hi;
                asm("mov.b64 {%0,%1},%2;" : "=f"(lo), "=f"(hi) : "l"(acc[r * 4 + q]));
                cmax[q * 2 + 0] = fmaxf(cmax[q * 2 + 0], lo);
                cmax[q * 2 + 1] = fmaxf(cmax[q * 2 + 1], hi);
            }
        }
    }
    __syncthreads();   // all H reads done before overlay
    ((float4*)(RED + ty * 256 + tx * 8))[0] = make_float4(cmax[0], cmax[1], cmax[2], cmax[3]);
    ((float4*)(RED + ty * 256 + tx * 8))[1] = make_float4(cmax[4], cmax[5], cmax[6], cmax[7]);
    __syncthreads();
    {
        int col = tid;
        float v = RED[col];
        #pragma unroll
        for (int t = 1; t < 8; t++) v = fmaxf(v, RED[t * 256 + col]);
        out[(long long)m * COUT + col] = v + b2[col];   // nv >= 1 (center itself)
    }
}

// ---------------------------------------------------------------------------
// Kernel 3: auxiliary tuple outputs (pos_dst, batch_dst, lframes_dst)
// ---------------------------------------------------------------------------
__global__ void extras_kernel(const float* __restrict__ pos, const int* __restrict__ batch,
                              const float* __restrict__ lframes, float* __restrict__ out)
{
    int m = blockIdx.x * blockDim.x + threadIdx.x;
    if (m >= Mc) return;
    int c = m * CSTRIDE;
    long long o = (long long)Mc * COUT;
    out[o + m * 3 + 0] = pos[c * 3 + 0];
    out[o + m * 3 + 1] = pos[c * 3 + 1];
    out[o + m * 3 + 2] = pos[c * 3 + 2];
    o += (long long)Mc * 3;
    out[o + m] = (float)batch[c];
    o += Mc;
    #pragma unroll
    for (int j = 0; j < 9; j++) out[o + m * 9 + j] = lframes[c * 9 + j];
}

// ---------------------------------------------------------------------------
extern "C" void kernel_launch(void* const* d_in, const int* in_sizes, int n_in,
                              void* d_out, int out_size)
{
    const float* x       = (const float*)d_in[0];
    const float* pos     = (const float*)d_in[1];
    const int*   batch   = (const int*)  d_in[2];
    const float* lframes = (const float*)d_in[3];
    const float* W1      = (const float*)d_in[4];
    const float* b1      = (const float*)d_in[5];
    const float* W2      = (const float*)d_in[6];
    const float* b2      = (const float*)d_in[7];
    float* out = (float*)d_out;

    float* P_buf; cudaGetSymbolAddress((void**)&P_buf, g_P);
    float* D_buf; cudaGetSymbolAddress((void**)&D_buf, g_D);

    int smem_bytes = (Kn * HID + HID + 3 * HID + 16) * (int)sizeof(float);
    cudaFuncSetAttribute(edge_mlp_kernel,
                         cudaFuncAttributeMaxDynamicSharedMemorySize, smem_bytes);

    ball_query_kernel<<<Mc, 256>>>(pos);
    pre_gemm_kernel<<<Npts / 64, 256>>>(x, W1, nullptr, P_buf, 1);           // P = x @ W1a
    pre_gemm_kernel<<<Mc / 64, 256>>>(x, W1 + CIN * HID, b1, D_buf, CSTRIDE); // D = x_dst @ W1b + b1
    edge_mlp_kernel<<<Mc, 256, smem_bytes>>>(pos, lframes, W1, W2, b2, out);

    long long full = (long long)Mc * COUT + (long long)Mc * 13;
    if ((long long)out_size >= full)
        extras_kernel<<<(Mc + 255) / 256, 256>>>(pos, batch, lframes, out);
}

// round 14
// speedup vs baseline: 1.4297x; 1.4291x over previous
#include <cuda_runtime.h>
#include <math.h>

#define Npts   16384
#define PER    2048
#define Mc     4096
#define Kn     64
#define R2v    0.0625f
#define CIN    128
#define HID    256
#define COUT   256
#define CSTRIDE 4

__device__ int   g_nbr[Mc * Kn];
__device__ int   g_cnt[Mc];
__device__ float g_P[Npts * HID];   // x @ W1[0:128]          (16 MB, L2-resident)
__device__ float g_D[Mc * HID];     // x_dst @ W1[128:256]+b1 (4 MB)

// ---------------------------------------------------------------------------
// Kernel 1: ball query. One block per center. Collect in-radius candidates
// (same batch block), bitonic-sort by packed (d2|idx) key, keep 64 nearest.
// ---------------------------------------------------------------------------
__global__ void __launch_bounds__(256) ball_query_kernel(const float* __restrict__ pos)
{
    __shared__ unsigned long long s[PER];
    __shared__ int cnt;
    int m = blockIdx.x;
    int c = m * CSTRIDE;
    int base = (c / PER) * PER;

    if (threadIdx.x == 0) cnt = 0;
    __syncthreads();

    float px = pos[c * 3 + 0], py = pos[c * 3 + 1], pz = pos[c * 3 + 2];
    for (int t = threadIdx.x; t < PER; t += blockDim.x) {
        int n = base + t;
        float dx = pos[n * 3 + 0] - px;
        float dy = pos[n * 3 + 1] - py;
        float dz = pos[n * 3 + 2] - pz;
        float d2 = dx * dx + dy * dy + dz * dz;
        if (d2 <= R2v) {
            int p = atomicAdd(&cnt, 1);
            s[p] = (((unsigned long long)__float_as_uint(d2)) << 32) | (unsigned)n;
        }
    }
    __syncthreads();
    int count = cnt;

    if (count > Kn) {
        int P = Kn;
        while (P < count) P <<= 1;
        for (int t = count + threadIdx.x; t < P; t += blockDim.x) s[t] = ~0ull;
        __syncthreads();
        for (int k2 = 2; k2 <= P; k2 <<= 1) {
            for (int j = k2 >> 1; j > 0; j >>= 1) {
                for (int i = threadIdx.x; i < P; i += blockDim.x) {
                    int ix = i ^ j;
                    if (ix > i) {
                        unsigned long long a = s[i], b = s[ix];
                        bool up = ((i & k2) == 0);
                        if ((a > b) == up) { s[i] = b; s[ix] = a; }
                    }
                }
                __syncthreads();
            }
        }
    }
    int nv = count < Kn ? count : Kn;
    for (int k = threadIdx.x; k < Kn; k += blockDim.x)
        g_nbr[m * Kn + k] = (k < nv) ? (int)(unsigned)(s[k] & 0xffffffffu) : c;
    if (threadIdx.x == 0) g_cnt[m] = nv;
}

// ---------------------------------------------------------------------------
// Kernel P: out[i] = X[i*rstride] @ W (+bias). 64 rows x 256 cols per block,
// K=128. 8x8 register tile, f32x2 FMAs, B pairs loaded pre-packed as b64.
// ---------------------------------------------------------------------------
__global__ void __launch_bounds__(256, 2) pre_gemm_kernel(
    const float* __restrict__ X, const float* __restrict__ W,
    const float* __restrict__ bias, float* __restrict__ out, int rstride)
{
    __shared__ float A[Kn * CIN];
    int r0 = blockIdx.x * 64;
    int tid = threadIdx.x;
    int ty = tid >> 5, tx = tid & 31;

    for (int k = ty; k < 64; k += 8) {
        const float4* src = (const float4*)(X + (long long)(r0 + k) * rstride * CIN);
        ((float4*)(A + k * CIN))[tx] = __ldg(src + tx);
    }
    __syncthreads();

    unsigned long long acc[32];
    #pragma unroll
    for (int i = 0; i < 32; i++) acc[i] = 0ull;

    const float* arow = A + (ty * 8) * CIN;
    #pragma unroll 4
    for (int kk = 0; kk < CIN; kk++) {
        const ulonglong2* wp = (const ulonglong2*)(W + (long long)kk * HID + tx * 8);
        ulonglong2 bA = __ldg(wp);
        ulonglong2 bB = __ldg(wp + 1);
        #pragma unroll
        for (int r = 0; r < 8; r++) {
            float a = arow[r * CIN + kk];
            unsigned long long aa;
            asm("mov.b64 %0,{%1,%1};" : "=l"(aa) : "f"(a));
            asm("fma.rn.f32x2 %0,%1,%2,%0;" : "+l"(acc[r * 4 + 0]) : "l"(aa), "l"(bA.x));
            asm("fma.rn.f32x2 %0,%1,%2,%0;" : "+l"(acc[r * 4 + 1]) : "l"(aa), "l"(bA.y));
            asm("fma.rn.f32x2 %0,%1,%2,%0;" : "+l"(acc[r * 4 + 2]) : "l"(aa), "l"(bB.x));
            asm("fma.rn.f32x2 %0,%1,%2,%0;" : "+l"(acc[r * 4 + 3]) : "l"(aa), "l"(bB.y));
        }
    }

    float bv[8];
    #pragma unroll
    for (int q = 0; q < 8; q++) bv[q] = bias ? bias[tx * 8 + q] : 0.f;
    #pragma unroll
    for (int r = 0; r < 8; r++) {
        float f[8];
        #pragma unroll
        for (int q = 0; q < 4; q++)
            asm("mov.b64 {%0,%1},%2;" : "=f"(f[q * 2]), "=f"(f[q * 2 + 1]) : "l"(acc[r * 4 + q]));
        #pragma unroll
        for (int q = 0; q < 8; q++) f[q] += bv[q];
        float* op = out + (long long)(r0 + ty * 8 + r) * HID + tx * 8;
        ((float4*)op)[0] = make_float4(f[0], f[1], f[2], f[3]);
        ((float4*)op)[1] = make_float4(f[4], f[5], f[6], f[7]);
    }
}

// ---------------------------------------------------------------------------
// Kernel 2: per-center. H[k] = relu(P[nbr_k] + D[m] + rel_loc @ W1c), then
// GEMM2 (H @ W2) with fused masked-max epilogue. 256 thr, 8x8 tile, f32x2.
// __launch_bounds__(256,2): cap at 128 regs so 2 CTAs co-reside per SM
// (occupancy was the binder: 132 regs -> 1 CTA -> fma pipe 41%, issue 27%).
// ---------------------------------------------------------------------------
__global__ void __launch_bounds__(256, 2) edge_mlp_kernel(
    const float* __restrict__ pos, const float* __restrict__ lframes,
    const float* __restrict__ W1, const float* __restrict__ W2,
    const float* __restrict__ b2, float* __restrict__ out)
{
    extern __shared__ float smem[];
    float* H   = smem;                 // [64][256]
    float* Dsh = H + Kn * HID;         // [256]
    float* Wc  = Dsh + HID;            // [3][256]  W1 rows 256..258
    float* AUX = Wc + 3 * HID;         // pos_dst(3), lframe(9)
    float* RED = H;                    // overlay after GEMM2 reads complete

    int m = blockIdx.x;
    int c = m * CSTRIDE;
    int tid = threadIdx.x;
    int ty = tid >> 5, tx = tid & 31;

    if (tid < 64) ((float4*)Dsh)[tid] = __ldg((const float4*)(g_D + (long long)m * HID) + tid);
    if (tid < 192) ((float4*)Wc)[tid] = __ldg((const float4*)(W1 + 256 * HID) + tid);
    if (tid >= 192 && tid < 195) AUX[tid - 192] = pos[c * 3 + (tid - 192)];
    if (tid >= 195 && tid < 204) AUX[3 + tid - 195] = lframes[c * 9 + (tid - 195)];
    __syncthreads();

    int nv = g_cnt[m];

    // Gather P rows + activation
    for (int k = ty; k < Kn; k += 8) {
        int n = g_nbr[m * Kn + k];
        float rx = __ldg(pos + n * 3 + 0) - AUX[0];
        float ry = __ldg(pos + n * 3 + 1) - AUX[1];
        float rz = __ldg(pos + n * 3 + 2) - AUX[2];
        float e0 = AUX[3] * rx + AUX[4] * ry + AUX[5] * rz;
        float e1 = AUX[6] * rx + AUX[7] * ry + AUX[8] * rz;
        float e2 = AUX[9] * rx + AUX[10] * ry + AUX[11] * rz;
        const float4* pr = (const float4*)(g_P + (long long)n * HID);
        #pragma unroll
        for (int j = tx; j < 64; j += 32) {
            float4 p = __ldg(pr + j);
            float4 d = ((float4*)Dsh)[j];
            float4 w0 = ((float4*)Wc)[j];
            float4 w1 = ((float4*)(Wc + HID))[j];
            float4 w2 = ((float4*)(Wc + 2 * HID))[j];
            float4 v;
            v.x = fmaxf(p.x + d.x + e0 * w0.x + e1 * w1.x + e2 * w2.x, 0.f);
            v.y = fmaxf(p.y + d.y + e0 * w0.y + e1 * w1.y + e2 * w2.y, 0.f);
            v.z = fmaxf(p.z + d.z + e0 * w0.z + e1 * w1.z + e2 * w2.z, 0.f);
            v.w = fmaxf(p.w + d.w + e0 * w0.w + e1 * w1.w + e2 * w2.w, 0.f);
            ((float4*)(H + k * HID))[j] = v;
        }
    }
    __syncthreads();

    // GEMM2: msg = H @ W2 (b2 folded post-max)
    unsigned long long acc[32];
    #pragma unroll
    for (int i = 0; i < 32; i++) acc[i] = 0ull;
    {
        const float* hrow = H + (ty * 8) * HID;
        #pragma unroll 4
        for (int kk = 0; kk < HID; kk++) {
            const ulonglong2* wp = (const ulonglong2*)(W2 + (long long)kk * COUT + tx * 8);
            ulonglong2 bA = __ldg(wp);
            ulonglong2 bB = __ldg(wp + 1);
            #pragma unroll
            for (int r = 0; r < 8; r++) {
                float a = hrow[r * HID + kk];
                unsigned long long aa;
                asm("mov.b64 %0,{%1,%1};" : "=l"(aa) : "f"(a));
                asm("fma.rn.f32x2 %0,%1,%2,%0;" : "+l"(acc[r * 4 + 0]) : "l"(aa), "l"(bA.x));
                asm("fma.rn.f32x2 %0,%1,%2,%0;" : "+l"(acc[r * 4 + 1]) : "l"(aa), "l"(bA.y));
                asm("fma.rn.f32x2 %0,%1,%2,%0;" : "+l"(acc[r * 4 + 2]) : "l"(aa), "l"(bB.x));
                asm("fma.rn.f32x2 %0,%1,%2,%0;" : "+l"(acc[r * 4 + 3]) : "l"(aa), "l"(bB.y));
            }
        }
    }

    // Masked max over this thread's 8 rows
    float cmax[8];
    #pragma unroll
    for (int q = 0; q < 8; q++) cmax[q] = -3.402823466e38f;
    #pragma unroll
    for (int r = 0; r < 8; r++) {
        if (ty * 8 + r < nv) {
            #pragma unroll
            for (int q = 0; q < 4; q++) {
                float lo, hi;
                asm("mov.b64 {%0,%1},%2;" : "=f"(lo), "=f"(hi) : "l"(acc[r * 4 + q]));
                cmax[q * 2 + 0] = fmaxf(cmax[q * 2 + 0], lo);
                cmax[q * 2 + 1] = fmaxf(cmax[q * 2 + 1], hi);
            }
        }
    }
    __syncthreads();   // all H reads done before overlay
    ((float4*)(RED + ty * 256 + tx * 8))[0] = make_float4(cmax[0], cmax[1], cmax[2], cmax[3]);
    ((float4*)(RED + ty * 256 + tx * 8))[1] = make_float4(cmax[4], cmax[5], cmax[6], cmax[7]);
    __syncthreads();
    {
        int col = tid;
        float v = RED[col];
        #pragma unroll
        for (int t = 1; t < 8; t++) v = fmaxf(v, RED[t * 256 + col]);
        out[(long long)m * COUT + col] = v + b2[col];   // nv >= 1 (center itself)
    }
}

// ---------------------------------------------------------------------------
// Kernel 3: auxiliary tuple outputs (pos_dst, batch_dst, lframes_dst)
// ---------------------------------------------------------------------------
__global__ void extras_kernel(const float* __restrict__ pos, const int* __restrict__ batch,
                              const float* __restrict__ lframes, float* __restrict__ out)
{
    int m = blockIdx.x * blockDim.x + threadIdx.x;
    if (m >= Mc) return;
    int c = m * CSTRIDE;
    long long o = (long long)Mc * COUT;
    out[o + m * 3 + 0] = pos[c * 3 + 0];
    out[o + m * 3 + 1] = pos[c * 3 + 1];
    out[o + m * 3 + 2] = pos[c * 3 + 2];
    o += (long long)Mc * 3;
    out[o + m] = (float)batch[c];
    o += Mc;
    #pragma unroll
    for (int j = 0; j < 9; j++) out[o + m * 9 + j] = lframes[c * 9 + j];
}

// ---------------------------------------------------------------------------
extern "C" void kernel_launch(void* const* d_in, const int* in_sizes, int n_in,
                              void* d_out, int out_size)
{
    const float* x       = (const float*)d_in[0];
    const float* pos     = (const float*)d_in[1];
    const int*   batch   = (const int*)  d_in[2];
    const float* lframes = (const float*)d_in[3];
    const float* W1      = (const float*)d_in[4];
    const float* b1      = (const float*)d_in[5];
    const float* W2      = (const float*)d_in[6];
    const float* b2      = (const float*)d_in[7];
    float* out = (float*)d_out;

    float* P_buf; cudaGetSymbolAddress((void**)&P_buf, g_P);
    float* D_buf; cudaGetSymbolAddress((void**)&D_buf, g_D);

    int smem_bytes = (Kn * HID + HID + 3 * HID + 16) * (int)sizeof(float);
    cudaFuncSetAttribute(edge_mlp_kernel,
                         cudaFuncAttributeMaxDynamicSharedMemorySize, smem_bytes);

    ball_query_kernel<<<Mc, 256>>>(pos);
    pre_gemm_kernel<<<Npts / 64, 256>>>(x, W1, nullptr, P_buf, 1);            // P = x @ W1a
    pre_gemm_kernel<<<Mc / 64, 256>>>(x, W1 + CIN * HID, b1, D_buf, CSTRIDE); // D = x_dst @ W1b + b1
    edge_mlp_kernel<<<Mc, 256, smem_bytes>>>(pos, lframes, W1, W2, b2, out);

    long long full = (long long)Mc * COUT + (long long)Mc * 13;
    if ((long long)out_size >= full)
        extras_kernel<<<(Mc + 255) / 256, 256>>>(pos, batch, lframes, out);
}

// round 15
// speedup vs baseline: 1.4564x; 1.0187x over previous
#include <cuda_runtime.h>
#include <math.h>

#define Npts   16384
#define PER    2048
#define Mc     4096
#define Kn     64
#define R2v    0.0625f
#define CIN    128
#define HID    256
#define COUT   256
#define CSTRIDE 4

__device__ int   g_nbr[Mc * Kn];
__device__ int   g_cnt[Mc];
__device__ float g_P[Npts * HID];   // x @ W1[0:128]          (16 MB, L2-resident)
__device__ float g_D[Mc * HID];     // x_dst @ W1[128:256]+b1 (4 MB)

// ---------------------------------------------------------------------------
// Kernel 1: ball query. One block per center. Collect in-radius candidates
// (same batch block), bitonic-sort by packed (d2|idx) key, keep 64 nearest.
// ---------------------------------------------------------------------------
__global__ void __launch_bounds__(256) ball_query_kernel(const float* __restrict__ pos)
{
    __shared__ unsigned long long s[PER];
    __shared__ int cnt;
    int m = blockIdx.x;
    int c = m * CSTRIDE;
    int base = (c / PER) * PER;

    if (threadIdx.x == 0) cnt = 0;
    __syncthreads();

    float px = pos[c * 3 + 0], py = pos[c * 3 + 1], pz = pos[c * 3 + 2];
    for (int t = threadIdx.x; t < PER; t += blockDim.x) {
        int n = base + t;
        float dx = pos[n * 3 + 0] - px;
        float dy = pos[n * 3 + 1] - py;
        float dz = pos[n * 3 + 2] - pz;
        float d2 = dx * dx + dy * dy + dz * dz;
        if (d2 <= R2v) {
            int p = atomicAdd(&cnt, 1);
            s[p] = (((unsigned long long)__float_as_uint(d2)) << 32) | (unsigned)n;
        }
    }
    __syncthreads();
    int count = cnt;

    if (count > Kn) {
        int P = Kn;
        while (P < count) P <<= 1;
        for (int t = count + threadIdx.x; t < P; t += blockDim.x) s[t] = ~0ull;
        __syncthreads();
        for (int k2 = 2; k2 <= P; k2 <<= 1) {
            for (int j = k2 >> 1; j > 0; j >>= 1) {
                for (int i = threadIdx.x; i < P; i += blockDim.x) {
                    int ix = i ^ j;
                    if (ix > i) {
                        unsigned long long a = s[i], b = s[ix];
                        bool up = ((i & k2) == 0);
                        if ((a > b) == up) { s[i] = b; s[ix] = a; }
                    }
                }
                __syncthreads();
            }
        }
    }
    int nv = count < Kn ? count : Kn;
    for (int k = threadIdx.x; k < Kn; k += blockDim.x)
        g_nbr[m * Kn + k] = (k < nv) ? (int)(unsigned)(s[k] & 0xffffffffu) : c;
    if (threadIdx.x == 0) g_cnt[m] = nv;
}

// ---------------------------------------------------------------------------
// Kernel P: out[i] = X[i*rstride] @ W (+bias). 64 rows x 256 cols per block,
// K=128. 8x8 register tile, f32x2 FMAs, B pairs loaded pre-packed as b64.
// ---------------------------------------------------------------------------
__global__ void __launch_bounds__(256, 2) pre_gemm_kernel(
    const float* __restrict__ X, const float* __restrict__ W,
    const float* __restrict__ bias, float* __restrict__ out, int rstride)
{
    __shared__ float A[Kn * CIN];
    int r0 = blockIdx.x * 64;
    int tid = threadIdx.x;
    int ty = tid >> 5, tx = tid & 31;

    for (int k = ty; k < 64; k += 8) {
        const float4* src = (const float4*)(X + (long long)(r0 + k) * rstride * CIN);
        ((float4*)(A + k * CIN))[tx] = __ldg(src + tx);
    }
    __syncthreads();

    unsigned long long acc[32];
    #pragma unroll
    for (int i = 0; i < 32; i++) acc[i] = 0ull;

    const float* arow = A + (ty * 8) * CIN;
    #pragma unroll 4
    for (int kk = 0; kk < CIN; kk++) {
        const ulonglong2* wp = (const ulonglong2*)(W + (long long)kk * HID + tx * 8);
        ulonglong2 bA = __ldg(wp);
        ulonglong2 bB = __ldg(wp + 1);
        #pragma unroll
        for (int r = 0; r < 8; r++) {
            float a = arow[r * CIN + kk];
            unsigned long long aa;
            asm("mov.b64 %0,{%1,%1};" : "=l"(aa) : "f"(a));
            asm("fma.rn.f32x2 %0,%1,%2,%0;" : "+l"(acc[r * 4 + 0]) : "l"(aa), "l"(bA.x));
            asm("fma.rn.f32x2 %0,%1,%2,%0;" : "+l"(acc[r * 4 + 1]) : "l"(aa), "l"(bA.y));
            asm("fma.rn.f32x2 %0,%1,%2,%0;" : "+l"(acc[r * 4 + 2]) : "l"(aa), "l"(bB.x));
            asm("fma.rn.f32x2 %0,%1,%2,%0;" : "+l"(acc[r * 4 + 3]) : "l"(aa), "l"(bB.y));
        }
    }

    float bv[8];
    #pragma unroll
    for (int q = 0; q < 8; q++) bv[q] = bias ? bias[tx * 8 + q] : 0.f;
    #pragma unroll
    for (int r = 0; r < 8; r++) {
        float f[8];
        #pragma unroll
        for (int q = 0; q < 4; q++)
            asm("mov.b64 {%0,%1},%2;" : "=f"(f[q * 2]), "=f"(f[q * 2 + 1]) : "l"(acc[r * 4 + q]));
        #pragma unroll
        for (int q = 0; q < 8; q++) f[q] += bv[q];
        float* op = out + (long long)(r0 + ty * 8 + r) * HID + tx * 8;
        ((float4*)op)[0] = make_float4(f[0], f[1], f[2], f[3]);
        ((float4*)op)[1] = make_float4(f[4], f[5], f[6], f[7]);
    }
}

// ---------------------------------------------------------------------------
// Kernel 2: per-center. H[k] = relu(P[nbr_k] + D[m] + rel_loc @ W1c), then
// GEMM2 (H @ W2) with fused masked-max epilogue. 256 thr, 8x8 tile, f32x2.
// GEMM2 K-loop unrolled by 4: H-row reads via LDS.128 broadcast (L1
// wavefronts/kk: 16 -> 10; L1tex was the 82% binder in R14).
// ---------------------------------------------------------------------------
__global__ void __launch_bounds__(256, 2) edge_mlp_kernel(
    const float* __restrict__ pos, const float* __restrict__ lframes,
    const float* __restrict__ W1, const float* __restrict__ W2,
    const float* __restrict__ b2, float* __restrict__ out)
{
    extern __shared__ float smem[];
    float* H   = smem;                 // [64][256]
    float* Dsh = H + Kn * HID;         // [256]
    float* Wc  = Dsh + HID;            // [3][256]  W1 rows 256..258
    float* AUX = Wc + 3 * HID;         // pos_dst(3), lframe(9)
    float* RED = H;                    // overlay after GEMM2 reads complete

    int m = blockIdx.x;
    int c = m * CSTRIDE;
    int tid = threadIdx.x;
    int ty = tid >> 5, tx = tid & 31;

    if (tid < 64) ((float4*)Dsh)[tid] = __ldg((const float4*)(g_D + (long long)m * HID) + tid);
    if (tid < 192) ((float4*)Wc)[tid] = __ldg((const float4*)(W1 + 256 * HID) + tid);
    if (tid >= 192 && tid < 195) AUX[tid - 192] = pos[c * 3 + (tid - 192)];
    if (tid >= 195 && tid < 204) AUX[3 + tid - 195] = lframes[c * 9 + (tid - 195)];
    __syncthreads();

    int nv = g_cnt[m];

    // Gather P rows + activation
    for (int k = ty; k < Kn; k += 8) {
        int n = g_nbr[m * Kn + k];
        float rx = __ldg(pos + n * 3 + 0) - AUX[0];
        float ry = __ldg(pos + n * 3 + 1) - AUX[1];
        float rz = __ldg(pos + n * 3 + 2) - AUX[2];
        float e0 = AUX[3] * rx + AUX[4] * ry + AUX[5] * rz;
        float e1 = AUX[6] * rx + AUX[7] * ry + AUX[8] * rz;
        float e2 = AUX[9] * rx + AUX[10] * ry + AUX[11] * rz;
        const float4* pr = (const float4*)(g_P + (long long)n * HID);
        #pragma unroll
        for (int j = tx; j < 64; j += 32) {
            float4 p = __ldg(pr + j);
            float4 d = ((float4*)Dsh)[j];
            float4 w0 = ((float4*)Wc)[j];
            float4 w1 = ((float4*)(Wc + HID))[j];
            float4 w2 = ((float4*)(Wc + 2 * HID))[j];
            float4 v;
            v.x = fmaxf(p.x + d.x + e0 * w0.x + e1 * w1.x + e2 * w2.x, 0.f);
            v.y = fmaxf(p.y + d.y + e0 * w0.y + e1 * w1.y + e2 * w2.y, 0.f);
            v.z = fmaxf(p.z + d.z + e0 * w0.z + e1 * w1.z + e2 * w2.z, 0.f);
            v.w = fmaxf(p.w + d.w + e0 * w0.w + e1 * w1.w + e2 * w2.w, 0.f);
            ((float4*)(H + k * HID))[j] = v;
        }
    }
    __syncthreads();

    // GEMM2: msg = H @ W2 (b2 folded post-max). kk unrolled x4, LDS.128 H reads.
    unsigned long long acc[32];
    #pragma unroll
    for (int i = 0; i < 32; i++) acc[i] = 0ull;
    {
        const float* hrow = H + (ty * 8) * HID;
        const char* w2base = (const char*)(W2 + tx * 8);
        for (int kk = 0; kk < HID; kk += 4) {
            float4 hv[8];
            #pragma unroll
            for (int r = 0; r < 8; r++)
                hv[r] = *(const float4*)(hrow + r * HID + kk);
            #pragma unroll
            for (int j = 0; j < 4; j++) {
                const ulonglong2* wp =
                    (const ulonglong2*)(w2base + (long long)(kk + j) * (COUT * 4));
                ulonglong2 bA = __ldg(wp);
                ulonglong2 bB = __ldg(wp + 1);
                #pragma unroll
                for (int r = 0; r < 8; r++) {
                    float a = (j == 0) ? hv[r].x : (j == 1) ? hv[r].y
                            : (j == 2) ? hv[r].z : hv[r].w;
                    unsigned long long aa;
                    asm("mov.b64 %0,{%1,%1};" : "=l"(aa) : "f"(a));
                    asm("fma.rn.f32x2 %0,%1,%2,%0;" : "+l"(acc[r * 4 + 0]) : "l"(aa), "l"(bA.x));
                    asm("fma.rn.f32x2 %0,%1,%2,%0;" : "+l"(acc[r * 4 + 1]) : "l"(aa), "l"(bA.y));
                    asm("fma.rn.f32x2 %0,%1,%2,%0;" : "+l"(acc[r * 4 + 2]) : "l"(aa), "l"(bB.x));
                    asm("fma.rn.f32x2 %0,%1,%2,%0;" : "+l"(acc[r * 4 + 3]) : "l"(aa), "l"(bB.y));
                }
            }
        }
    }

    // Masked max over this thread's 8 rows
    float cmax[8];
    #pragma unroll
    for (int q = 0; q < 8; q++) cmax[q] = -3.402823466e38f;
    #pragma unroll
    for (int r = 0; r < 8; r++) {
        if (ty * 8 + r < nv) {
            #pragma unroll
            for (int q = 0; q < 4; q++) {
                float lo, hi;
                asm("mov.b64 {%0,%1},%2;" : "=f"(lo), "=f"(hi) : "l"(acc[r * 4 + q]));
                cmax[q * 2 + 0] = fmaxf(cmax[q * 2 + 0], lo);
                cmax[q * 2 + 1] = fmaxf(cmax[q * 2 + 1], hi);
            }
        }
    }
    __syncthreads();   // all H reads done before overlay
    ((float4*)(RED + ty * 256 + tx * 8))[0] = make_float4(cmax[0], cmax[1], cmax[2], cmax[3]);
    ((float4*)(RED + ty * 256 + tx * 8))[1] = make_float4(cmax[4], cmax[5], cmax[6], cmax[7]);
    __syncthreads();
    {
        int col = tid;
        float v = RED[col];
        #pragma unroll
        for (int t = 1; t < 8; t++) v = fmaxf(v, RED[t * 256 + col]);
        out[(long long)m * COUT + col] = v + b2[col];   // nv >= 1 (center itself)
    }
}

// ---------------------------------------------------------------------------
// Kernel 3: auxiliary tuple outputs (pos_dst, batch_dst, lframes_dst)
// ---------------------------------------------------------------------------
__global__ void extras_kernel(const float* __restrict__ pos, const int* __restrict__ batch,
                              const float* __restrict__ lframes, float* __restrict__ out)
{
    int m = blockIdx.x * blockDim.x + threadIdx.x;
    if (m >= Mc) return;
    int c = m * CSTRIDE;
    long long o = (long long)Mc * COUT;
    out[o + m * 3 + 0] = pos[c * 3 + 0];
    out[o + m * 3 + 1] = pos[c * 3 + 1];
    out[o + m * 3 + 2] = pos[c * 3 + 2];
    o += (long long)Mc * 3;
    out[o + m] = (float)batch[c];
    o += Mc;
    #pragma unroll
    for (int j = 0; j < 9; j++) out[o + m * 9 + j] = lframes[c * 9 + j];
}

// ---------------------------------------------------------------------------
extern "C" void kernel_launch(void* const* d_in, const int* in_sizes, int n_in,
                              void* d_out, int out_size)
{
    const float* x       = (const float*)d_in[0];
    const float* pos     = (const float*)d_in[1];
    const int*   batch   = (const int*)  d_in[2];
    const float* lframes = (const float*)d_in[3];
    const float* W1      = (const float*)d_in[4];
    const float* b1      = (const float*)d_in[5];
    const float* W2      = (const float*)d_in[6];
    const float* b2      = (const float*)d_in[7];
    float* out = (float*)d_out;

    float* P_buf; cudaGetSymbolAddress((void**)&P_buf, g_P);
    float* D_buf; cudaGetSymbolAddress((void**)&D_buf, g_D);

    int smem_bytes = (Kn * HID + HID + 3 * HID + 16) * (int)sizeof(float);
    cudaFuncSetAttribute(edge_mlp_kernel,
                         cudaFuncAttributeMaxDynamicSharedMemorySize, smem_bytes);

    ball_query_kernel<<<Mc, 256>>>(pos);
    pre_gemm_kernel<<<Npts / 64, 256>>>(x, W1, nullptr, P_buf, 1);            // P = x @ W1a
    pre_gemm_kernel<<<Mc / 64, 256>>>(x, W1 + CIN * HID, b1, D_buf, CSTRIDE); // D = x_dst @ W1b + b1
    edge_mlp_kernel<<<Mc, 256, smem_bytes>>>(pos, lframes, W1, W2, b2, out);

    long long full = (long long)Mc * COUT + (long long)Mc * 13;
    if ((long long)out_size >= full)
        extras_kernel<<<(Mc + 255) / 256, 256>>>(pos, batch, lframes, out);
}

// round 16
// speedup vs baseline: 1.4566x; 1.0002x over previous
#include <cuda_runtime.h>
#include <math.h>

#define Npts   16384
#define PER    2048
#define Mc     4096
#define Kn     64
#define R2v    0.0625f
#define CIN    128
#define HID    256
#define COUT   256
#define CSTRIDE 4

__device__ int   g_nbr[Mc * Kn];
__device__ int   g_cnt[Mc];
__device__ float g_P[Npts * HID];   // x @ W1[0:128]          (16 MB, L2-resident)
__device__ float g_D[Mc * HID];     // x_dst @ W1[128:256]+b1 (4 MB)

// ---------------------------------------------------------------------------
// Kernel 1: ball query. One block per center. Collect in-radius candidates
// (same batch block), bitonic-sort by packed (d2|idx) key, keep 64 nearest.
// ---------------------------------------------------------------------------
__global__ void __launch_bounds__(256) ball_query_kernel(const float* __restrict__ pos)
{
    __shared__ unsigned long long s[PER];
    __shared__ int cnt;
    int m = blockIdx.x;
    int c = m * CSTRIDE;
    int base = (c / PER) * PER;

    if (threadIdx.x == 0) cnt = 0;
    __syncthreads();

    float px = pos[c * 3 + 0], py = pos[c * 3 + 1], pz = pos[c * 3 + 2];
    for (int t = threadIdx.x; t < PER; t += blockDim.x) {
        int n = base + t;
        float dx = pos[n * 3 + 0] - px;
        float dy = pos[n * 3 + 1] - py;
        float dz = pos[n * 3 + 2] - pz;
        float d2 = dx * dx + dy * dy + dz * dz;
        if (d2 <= R2v) {
            int p = atomicAdd(&cnt, 1);
            s[p] = (((unsigned long long)__float_as_uint(d2)) << 32) | (unsigned)n;
        }
    }
    __syncthreads();
    int count = cnt;

    if (count > Kn) {
        int P = Kn;
        while (P < count) P <<= 1;
        for (int t = count + threadIdx.x; t < P; t += blockDim.x) s[t] = ~0ull;
        __syncthreads();
        for (int k2 = 2; k2 <= P; k2 <<= 1) {
            for (int j = k2 >> 1; j > 0; j >>= 1) {
                for (int i = threadIdx.x; i < P; i += blockDim.x) {
                    int ix = i ^ j;
                    if (ix > i) {
                        unsigned long long a = s[i], b = s[ix];
                        bool up = ((i & k2) == 0);
                        if ((a > b) == up) { s[i] = b; s[ix] = a; }
                    }
                }
                __syncthreads();
            }
        }
    }
    int nv = count < Kn ? count : Kn;
    for (int k = threadIdx.x; k < Kn; k += blockDim.x)
        g_nbr[m * Kn + k] = (k < nv) ? (int)(unsigned)(s[k] & 0xffffffffu) : c;
    if (threadIdx.x == 0) g_cnt[m] = nv;
}

// ---------------------------------------------------------------------------
// Kernel P: out[i] = X[i*rstride] @ W (+bias). 64 rows x 256 cols per block,
// K=128. 8x8 register tile, f32x2 FMAs, B pairs loaded pre-packed as b64.
// ---------------------------------------------------------------------------
__global__ void __launch_bounds__(256, 2) pre_gemm_kernel(
    const float* __restrict__ X, const float* __restrict__ W,
    const float* __restrict__ bias, float* __restrict__ out, int rstride)
{
    __shared__ float A[Kn * CIN];
    int r0 = blockIdx.x * 64;
    int tid = threadIdx.x;
    int ty = tid >> 5, tx = tid & 31;

    for (int k = ty; k < 64; k += 8) {
        const float4* src = (const float4*)(X + (long long)(r0 + k) * rstride * CIN);
        ((float4*)(A + k * CIN))[tx] = __ldg(src + tx);
    }
    __syncthreads();

    unsigned long long acc[32];
    #pragma unroll
    for (int i = 0; i < 32; i++) acc[i] = 0ull;

    const float* arow = A + (ty * 8) * CIN;
    #pragma unroll 4
    for (int kk = 0; kk < CIN; kk++) {
        const ulonglong2* wp = (const ulonglong2*)(W + (long long)kk * HID + tx * 8);
        ulonglong2 bA = __ldg(wp);
        ulonglong2 bB = __ldg(wp + 1);
        #pragma unroll
        for (int r = 0; r < 8; r++) {
            float a = arow[r * CIN + kk];
            unsigned long long aa;
            asm("mov.b64 %0,{%1,%1};" : "=l"(aa) : "f"(a));
            asm("fma.rn.f32x2 %0,%1,%2,%0;" : "+l"(acc[r * 4 + 0]) : "l"(aa), "l"(bA.x));
            asm("fma.rn.f32x2 %0,%1,%2,%0;" : "+l"(acc[r * 4 + 1]) : "l"(aa), "l"(bA.y));
            asm("fma.rn.f32x2 %0,%1,%2,%0;" : "+l"(acc[r * 4 + 2]) : "l"(aa), "l"(bB.x));
            asm("fma.rn.f32x2 %0,%1,%2,%0;" : "+l"(acc[r * 4 + 3]) : "l"(aa), "l"(bB.y));
        }
    }

    float bv[8];
    #pragma unroll
    for (int q = 0; q < 8; q++) bv[q] = bias ? bias[tx * 8 + q] : 0.f;
    #pragma unroll
    for (int r = 0; r < 8; r++) {
        float f[8];
        #pragma unroll
        for (int q = 0; q < 4; q++)
            asm("mov.b64 {%0,%1},%2;" : "=f"(f[q * 2]), "=f"(f[q * 2 + 1]) : "l"(acc[r * 4 + q]));
        #pragma unroll
        for (int q = 0; q < 8; q++) f[q] += bv[q];
        float* op = out + (long long)(r0 + ty * 8 + r) * HID + tx * 8;
        ((float4*)op)[0] = make_float4(f[0], f[1], f[2], f[3]);
        ((float4*)op)[1] = make_float4(f[4], f[5], f[6], f[7]);
    }
}

// ---------------------------------------------------------------------------
// Kernel 2: per-center. H[k] = relu(P[nbr_k] + D[m] + rel_loc @ W1c), then
// GEMM2 (H @ W2) with fused masked-max epilogue. 256 thr, 8x8 tile, f32x2.
// GEMM2 K-loop unrolled by 4: H-row reads via LDS.128 broadcast (L1
// wavefronts/kk: 16 -> 10; L1tex was the 82% binder in R14).
// ---------------------------------------------------------------------------
__global__ void __launch_bounds__(256, 2) edge_mlp_kernel(
    const float* __restrict__ pos, const float* __restrict__ lframes,
    const float* __restrict__ W1, const float* __restrict__ W2,
    const float* __restrict__ b2, float* __restrict__ out)
{
    extern __shared__ float smem[];
    float* H   = smem;                 // [64][256]
    float* Dsh = H + Kn * HID;         // [256]
    float* Wc  = Dsh + HID;            // [3][256]  W1 rows 256..258
    float* AUX = Wc + 3 * HID;         // pos_dst(3), lframe(9)
    float* RED = H;                    // overlay after GEMM2 reads complete

    int m = blockIdx.x;
    int c = m * CSTRIDE;
    int tid = threadIdx.x;
    int ty = tid >> 5, tx = tid & 31;

    if (tid < 64) ((float4*)Dsh)[tid] = __ldg((const float4*)(g_D + (long long)m * HID) + tid);
    if (tid < 192) ((float4*)Wc)[tid] = __ldg((const float4*)(W1 + 256 * HID) + tid);
    if (tid >= 192 && tid < 195) AUX[tid - 192] = pos[c * 3 + (tid - 192)];
    if (tid >= 195 && tid < 204) AUX[3 + tid - 195] = lframes[c * 9 + (tid - 195)];
    __syncthreads();

    int nv = g_cnt[m];

    // Gather P rows + activation
    for (int k = ty; k < Kn; k += 8) {
        int n = g_nbr[m * Kn + k];
        float rx = __ldg(pos + n * 3 + 0) - AUX[0];
        float ry = __ldg(pos + n * 3 + 1) - AUX[1];
        float rz = __ldg(pos + n * 3 + 2) - AUX[2];
        float e0 = AUX[3] * rx + AUX[4] * ry + AUX[5] * rz;
        float e1 = AUX[6] * rx + AUX[7] * ry + AUX[8] * rz;
        float e2 = AUX[9] * rx + AUX[10] * ry + AUX[11] * rz;
        const float4* pr = (const float4*)(g_P + (long long)n * HID);
        #pragma unroll
        for (int j = tx; j < 64; j += 32) {
            float4 p = __ldg(pr + j);
            float4 d = ((float4*)Dsh)[j];
            float4 w0 = ((float4*)Wc)[j];
            float4 w1 = ((float4*)(Wc + HID))[j];
            float4 w2 = ((float4*)(Wc + 2 * HID))[j];
            float4 v;
            v.x = fmaxf(p.x + d.x + e0 * w0.x + e1 * w1.x + e2 * w2.x, 0.f);
            v.y = fmaxf(p.y + d.y + e0 * w0.y + e1 * w1.y + e2 * w2.y, 0.f);
            v.z = fmaxf(p.z + d.z + e0 * w0.z + e1 * w1.z + e2 * w2.z, 0.f);
            v.w = fmaxf(p.w + d.w + e0 * w0.w + e1 * w1.w + e2 * w2.w, 0.f);
            ((float4*)(H + k * HID))[j] = v;
        }
    }
    __syncthreads();

    // GEMM2: msg = H @ W2 (b2 folded post-max). kk unrolled x4, LDS.128 H reads.
    unsigned long long acc[32];
    #pragma unroll
    for (int i = 0; i < 32; i++) acc[i] = 0ull;
    {
        const float* hrow = H + (ty * 8) * HID;
        const char* w2base = (const char*)(W2 + tx * 8);
        for (int kk = 0; kk < HID; kk += 4) {
            float4 hv[8];
            #pragma unroll
            for (int r = 0; r < 8; r++)
                hv[r] = *(const float4*)(hrow + r * HID + kk);
            #pragma unroll
            for (int j = 0; j < 4; j++) {
                const ulonglong2* wp =
                    (const ulonglong2*)(w2base + (long long)(kk + j) * (COUT * 4));
                ulonglong2 bA = __ldg(wp);
                ulonglong2 bB = __ldg(wp + 1);
                #pragma unroll
                for (int r = 0; r < 8; r++) {
                    float a = (j == 0) ? hv[r].x : (j == 1) ? hv[r].y
                            : (j == 2) ? hv[r].z : hv[r].w;
                    unsigned long long aa;
                    asm("mov.b64 %0,{%1,%1};" : "=l"(aa) : "f"(a));
                    asm("fma.rn.f32x2 %0,%1,%2,%0;" : "+l"(acc[r * 4 + 0]) : "l"(aa), "l"(bA.x));
                    asm("fma.rn.f32x2 %0,%1,%2,%0;" : "+l"(acc[r * 4 + 1]) : "l"(aa), "l"(bA.y));
                    asm("fma.rn.f32x2 %0,%1,%2,%0;" : "+l"(acc[r * 4 + 2]) : "l"(aa), "l"(bB.x));
                    asm("fma.rn.f32x2 %0,%1,%2,%0;" : "+l"(acc[r * 4 + 3]) : "l"(aa), "l"(bB.y));
                }
            }
        }
    }

    // Masked max over this thread's 8 rows
    float cmax[8];
    #pragma unroll
    for (int q = 0; q < 8; q++) cmax[q] = -3.402823466e38f;
    #pragma unroll
    for (int r = 0; r < 8; r++) {
        if (ty * 8 + r < nv) {
            #pragma unroll
            for (int q = 0; q < 4; q++) {
                float lo, hi;
                asm("mov.b64 {%0,%1},%2;" : "=f"(lo), "=f"(hi) : "l"(acc[r * 4 + q]));
                cmax[q * 2 + 0] = fmaxf(cmax[q * 2 + 0], lo);
                cmax[q * 2 + 1] = fmaxf(cmax[q * 2 + 1], hi);
            }
        }
    }
    __syncthreads();   // all H reads done before overlay
    ((float4*)(RED + ty * 256 + tx * 8))[0] = make_float4(cmax[0], cmax[1], cmax[2], cmax[3]);
    ((float4*)(RED + ty * 256 + tx * 8))[1] = make_float4(cmax[4], cmax[5], cmax[6], cmax[7]);
    __syncthreads();
    {
        int col = tid;
        float v = RED[col];
        #pragma unroll
        for (int t = 1; t < 8; t++) v = fmaxf(v, RED[t * 256 + col]);
        out[(long long)m * COUT + col] = v + b2[col];   // nv >= 1 (center itself)
    }
}

// ---------------------------------------------------------------------------
// Kernel 3: auxiliary tuple outputs (pos_dst, batch_dst, lframes_dst)
// ---------------------------------------------------------------------------
__global__ void extras_kernel(const float* __restrict__ pos, const int* __restrict__ batch,
                              const float* __restrict__ lframes, float* __restrict__ out)
{
    int m = blockIdx.x * blockDim.x + threadIdx.x;
    if (m >= Mc) return;
    int c = m * CSTRIDE;
    long long o = (long long)Mc * COUT;
    out[o + m * 3 + 0] = pos[c * 3 + 0];
    out[o + m * 3 + 1] = pos[c * 3 + 1];
    out[o + m * 3 + 2] = pos[c * 3 + 2];
    o += (long long)Mc * 3;
    out[o + m] = (float)batch[c];
    o += Mc;
    #pragma unroll
    for (int j = 0; j < 9; j++) out[o + m * 9 + j] = lframes[c * 9 + j];
}

// ---------------------------------------------------------------------------
extern "C" void kernel_launch(void* const* d_in, const int* in_sizes, int n_in,
                              void* d_out, int out_size)
{
    const float* x       = (const float*)d_in[0];
    const float* pos     = (const float*)d_in[1];
    const int*   batch   = (const int*)  d_in[2];
    const float* lframes = (const float*)d_in[3];
    const float* W1      = (const float*)d_in[4];
    const float* b1      = (const float*)d_in[5];
    const float* W2      = (const float*)d_in[6];
    const float* b2      = (const float*)d_in[7];
    float* out = (float*)d_out;

    float* P_buf; cudaGetSymbolAddress((void**)&P_buf, g_P);
    float* D_buf; cudaGetSymbolAddress((void**)&D_buf, g_D);

    int smem_bytes = (Kn * HID + HID + 3 * HID + 16) * (int)sizeof(float);
    cudaFuncSetAttribute(edge_mlp_kernel,
                         cudaFuncAttributeMaxDynamicSharedMemorySize, smem_bytes);

    ball_query_kernel<<<Mc, 256>>>(pos);
    pre_gemm_kernel<<<Npts / 64, 256>>>(x, W1, nullptr, P_buf, 1);            // P = x @ W1a
    pre_gemm_kernel<<<Mc / 64, 256>>>(x, W1 + CIN * HID, b1, D_buf, CSTRIDE); // D = x_dst @ W1b + b1
    edge_mlp_kernel<<<Mc, 256, smem_bytes>>>(pos, lframes, W1, W2, b2, out);

    long long full = (long long)Mc * COUT + (long long)Mc * 13;
    if ((long long)out_size >= full)
        extras_kernel<<<(Mc + 255) / 256, 256>>>(pos, batch, lframes, out);
}

// round 17
// speedup vs baseline: 1.5386x; 1.0563x over previous
#include <cuda_runtime.h>
#include <math.h>

#define Npts   16384
#define PER    2048
#define Mc     4096
#define Kn     64
#define R2v    0.0625f
#define CIN    128
#define HID    256
#define COUT   256
#define CSTRIDE 4

__device__ int   g_nbr[Mc * Kn];
__device__ int   g_cnt[Mc];
__device__ float g_P[Npts * HID];   // x @ W1[0:128]          (16 MB, L2-resident)
__device__ float g_D[Mc * HID];     // x_dst @ W1[128:256]+b1 (4 MB)

// ---------------------------------------------------------------------------
// Kernel 1: ball query. One block per center. Collect in-radius candidates
// (same batch block), bitonic-sort by packed (d2|idx) key, keep 64 nearest.
// ---------------------------------------------------------------------------
__global__ void __launch_bounds__(256) ball_query_kernel(const float* __restrict__ pos)
{
    __shared__ unsigned long long s[PER];
    __shared__ int cnt;
    int m = blockIdx.x;
    int c = m * CSTRIDE;
    int base = (c / PER) * PER;

    if (threadIdx.x == 0) cnt = 0;
    __syncthreads();

    float px = pos[c * 3 + 0], py = pos[c * 3 + 1], pz = pos[c * 3 + 2];
    for (int t = threadIdx.x; t < PER; t += blockDim.x) {
        int n = base + t;
        float dx = pos[n * 3 + 0] - px;
        float dy = pos[n * 3 + 1] - py;
        float dz = pos[n * 3 + 2] - pz;
        float d2 = dx * dx + dy * dy + dz * dz;
        if (d2 <= R2v) {
            int p = atomicAdd(&cnt, 1);
            s[p] = (((unsigned long long)__float_as_uint(d2)) << 32) | (unsigned)n;
        }
    }
    __syncthreads();
    int count = cnt;

    if (count > Kn) {
        int P = Kn;
        while (P < count) P <<= 1;
        for (int t = count + threadIdx.x; t < P; t += blockDim.x) s[t] = ~0ull;
        __syncthreads();
        for (int k2 = 2; k2 <= P; k2 <<= 1) {
            for (int j = k2 >> 1; j > 0; j >>= 1) {
                for (int i = threadIdx.x; i < P; i += blockDim.x) {
                    int ix = i ^ j;
                    if (ix > i) {
                        unsigned long long a = s[i], b = s[ix];
                        bool up = ((i & k2) == 0);
                        if ((a > b) == up) { s[i] = b; s[ix] = a; }
                    }
                }
                __syncthreads();
            }
        }
    }
    int nv = count < Kn ? count : Kn;
    for (int k = threadIdx.x; k < Kn; k += blockDim.x)
        g_nbr[m * Kn + k] = (k < nv) ? (int)(unsigned)(s[k] & 0xffffffffu) : c;
    if (threadIdx.x == 0) g_cnt[m] = nv;
}

// ---------------------------------------------------------------------------
// Kernel P: out[i] = X[i*rstride] @ W (+bias). 64 rows x 256 cols per block.
// Thread tx owns cols {tx*4..+3} and {128+tx*4..+3}: each 16B weight LDG is
// warp-contiguous (4 wavefronts, was 8 with the strided tx*8 mapping).
// ---------------------------------------------------------------------------
__global__ void __launch_bounds__(256, 2) pre_gemm_kernel(
    const float* __restrict__ X, const float* __restrict__ W,
    const float* __restrict__ bias, float* __restrict__ out, int rstride)
{
    __shared__ float A[Kn * CIN];
    int r0 = blockIdx.x * 64;
    int tid = threadIdx.x;
    int ty = tid >> 5, tx = tid & 31;

    for (int k = ty; k < 64; k += 8) {
        const float4* src = (const float4*)(X + (long long)(r0 + k) * rstride * CIN);
        ((float4*)(A + k * CIN))[tx] = __ldg(src + tx);
    }
    __syncthreads();

    unsigned long long acc[32];
    #pragma unroll
    for (int i = 0; i < 32; i++) acc[i] = 0ull;

    const float* arow = A + (ty * 8) * CIN;
    #pragma unroll 4
    for (int kk = 0; kk < CIN; kk++) {
        ulonglong2 bA = __ldg((const ulonglong2*)(W + (long long)kk * HID + tx * 4));
        ulonglong2 bB = __ldg((const ulonglong2*)(W + (long long)kk * HID + 128 + tx * 4));
        #pragma unroll
        for (int r = 0; r < 8; r++) {
            float a = arow[r * CIN + kk];
            unsigned long long aa;
            asm("mov.b64 %0,{%1,%1};" : "=l"(aa) : "f"(a));
            asm("fma.rn.f32x2 %0,%1,%2,%0;" : "+l"(acc[r * 4 + 0]) : "l"(aa), "l"(bA.x));
            asm("fma.rn.f32x2 %0,%1,%2,%0;" : "+l"(acc[r * 4 + 1]) : "l"(aa), "l"(bA.y));
            asm("fma.rn.f32x2 %0,%1,%2,%0;" : "+l"(acc[r * 4 + 2]) : "l"(aa), "l"(bB.x));
            asm("fma.rn.f32x2 %0,%1,%2,%0;" : "+l"(acc[r * 4 + 3]) : "l"(aa), "l"(bB.y));
        }
    }

    float bv[8];
    #pragma unroll
    for (int q = 0; q < 4; q++) {
        bv[q]     = bias ? bias[tx * 4 + q]       : 0.f;
        bv[4 + q] = bias ? bias[128 + tx * 4 + q] : 0.f;
    }
    #pragma unroll
    for (int r = 0; r < 8; r++) {
        float f[8];
        #pragma unroll
        for (int q = 0; q < 4; q++)
            asm("mov.b64 {%0,%1},%2;" : "=f"(f[q * 2]), "=f"(f[q * 2 + 1]) : "l"(acc[r * 4 + q]));
        #pragma unroll
        for (int q = 0; q < 8; q++) f[q] += bv[(q >> 1 & 2) * 2 + (q & 1) + (q & 2)];
        // f layout: f[0..3] = cols tx*4..+3, f[4..7] = cols 128+tx*4..+3 ? fix below
        float* op = out + (long long)(r0 + ty * 8 + r) * HID;
        // recompute cleanly to avoid index confusion:
        float lo0, lo1, lo2, lo3, hi0, hi1, hi2, hi3;
        asm("mov.b64 {%0,%1},%2;" : "=f"(lo0), "=f"(lo1) : "l"(acc[r * 4 + 0]));
        asm("mov.b64 {%0,%1},%2;" : "=f"(lo2), "=f"(lo3) : "l"(acc[r * 4 + 1]));
        asm("mov.b64 {%0,%1},%2;" : "=f"(hi0), "=f"(hi1) : "l"(acc[r * 4 + 2]));
        asm("mov.b64 {%0,%1},%2;" : "=f"(hi2), "=f"(hi3) : "l"(acc[r * 4 + 3]));
        ((float4*)(op + tx * 4))[0] =
            make_float4(lo0 + bv[0], lo1 + bv[1], lo2 + bv[2], lo3 + bv[3]);
        ((float4*)(op + 128 + tx * 4))[0] =
            make_float4(hi0 + bv[4], hi1 + bv[5], hi2 + bv[6], hi3 + bv[7]);
    }
}

// ---------------------------------------------------------------------------
// Kernel 2: per-center. H[k] = relu(P[nbr_k] + D[m] + rel_loc @ W1c), then
// GEMM2 (H @ W2) with fused masked-max epilogue. 256 thr, 8x8 tile, f32x2.
// W2 cols per thread: {tx*4..+3} + {128+tx*4..+3} -> coalesced 16B LDGs
// (W2 L1 wavefronts 16 -> 8 per kk per warp; L1tex was the 84.6% binder).
// ---------------------------------------------------------------------------
__global__ void __launch_bounds__(256, 2) edge_mlp_kernel(
    const float* __restrict__ pos, const float* __restrict__ lframes,
    const float* __restrict__ W1, const float* __restrict__ W2,
    const float* __restrict__ b2, float* __restrict__ out)
{
    extern __shared__ float smem[];
    float* H   = smem;                 // [64][256]
    float* Dsh = H + Kn * HID;         // [256]
    float* Wc  = Dsh + HID;            // [3][256]  W1 rows 256..258
    float* AUX = Wc + 3 * HID;         // pos_dst(3), lframe(9)
    float* RED = H;                    // overlay after GEMM2 reads complete

    int m = blockIdx.x;
    int c = m * CSTRIDE;
    int tid = threadIdx.x;
    int ty = tid >> 5, tx = tid & 31;

    if (tid < 64) ((float4*)Dsh)[tid] = __ldg((const float4*)(g_D + (long long)m * HID) + tid);
    if (tid < 192) ((float4*)Wc)[tid] = __ldg((const float4*)(W1 + 256 * HID) + tid);
    if (tid >= 192 && tid < 195) AUX[tid - 192] = pos[c * 3 + (tid - 192)];
    if (tid >= 195 && tid < 204) AUX[3 + tid - 195] = lframes[c * 9 + (tid - 195)];
    __syncthreads();

    int nv = g_cnt[m];

    // Gather P rows + activation
    for (int k = ty; k < Kn; k += 8) {
        int n = g_nbr[m * Kn + k];
        float rx = __ldg(pos + n * 3 + 0) - AUX[0];
        float ry = __ldg(pos + n * 3 + 1) - AUX[1];
        float rz = __ldg(pos + n * 3 + 2) - AUX[2];
        float e0 = AUX[3] * rx + AUX[4] * ry + AUX[5] * rz;
        float e1 = AUX[6] * rx + AUX[7] * ry + AUX[8] * rz;
        float e2 = AUX[9] * rx + AUX[10] * ry + AUX[11] * rz;
        const float4* pr = (const float4*)(g_P + (long long)n * HID);
        #pragma unroll
        for (int j = tx; j < 64; j += 32) {
            float4 p = __ldg(pr + j);
            float4 d = ((float4*)Dsh)[j];
            float4 w0 = ((float4*)Wc)[j];
            float4 w1 = ((float4*)(Wc + HID))[j];
            float4 w2 = ((float4*)(Wc + 2 * HID))[j];
            float4 v;
            v.x = fmaxf(p.x + d.x + e0 * w0.x + e1 * w1.x + e2 * w2.x, 0.f);
            v.y = fmaxf(p.y + d.y + e0 * w0.y + e1 * w1.y + e2 * w2.y, 0.f);
            v.z = fmaxf(p.z + d.z + e0 * w0.z + e1 * w1.z + e2 * w2.z, 0.f);
            v.w = fmaxf(p.w + d.w + e0 * w0.w + e1 * w1.w + e2 * w2.w, 0.f);
            ((float4*)(H + k * HID))[j] = v;
        }
    }
    __syncthreads();

    // GEMM2: msg = H @ W2 (b2 folded post-max). kk unrolled x4, LDS.128 H reads,
    // coalesced W2 LDGs.
    unsigned long long acc[32];
    #pragma unroll
    for (int i = 0; i < 32; i++) acc[i] = 0ull;
    {
        const float* hrow = H + (ty * 8) * HID;
        const char* w2lo = (const char*)(W2 + tx * 4);
        const char* w2hi = (const char*)(W2 + 128 + tx * 4);
        for (int kk = 0; kk < HID; kk += 4) {
            float4 hv[8];
            #pragma unroll
            for (int r = 0; r < 8; r++)
                hv[r] = *(const float4*)(hrow + r * HID + kk);
            #pragma unroll
            for (int j = 0; j < 4; j++) {
                ulonglong2 bA = __ldg((const ulonglong2*)(w2lo + (long long)(kk + j) * (COUT * 4)));
                ulonglong2 bB = __ldg((const ulonglong2*)(w2hi + (long long)(kk + j) * (COUT * 4)));
                #pragma unroll
                for (int r = 0; r < 8; r++) {
                    float a = (j == 0) ? hv[r].x : (j == 1) ? hv[r].y
                            : (j == 2) ? hv[r].z : hv[r].w;
                    unsigned long long aa;
                    asm("mov.b64 %0,{%1,%1};" : "=l"(aa) : "f"(a));
                    asm("fma.rn.f32x2 %0,%1,%2,%0;" : "+l"(acc[r * 4 + 0]) : "l"(aa), "l"(bA.x));
                    asm("fma.rn.f32x2 %0,%1,%2,%0;" : "+l"(acc[r * 4 + 1]) : "l"(aa), "l"(bA.y));
                    asm("fma.rn.f32x2 %0,%1,%2,%0;" : "+l"(acc[r * 4 + 2]) : "l"(aa), "l"(bB.x));
                    asm("fma.rn.f32x2 %0,%1,%2,%0;" : "+l"(acc[r * 4 + 3]) : "l"(aa), "l"(bB.y));
                }
            }
        }
    }

    // Masked max over this thread's 8 rows.
    // cmax[0..3] = cols tx*4..+3 ; cmax[4..7] = cols 128+tx*4..+3
    float cmax[8];
    #pragma unroll
    for (int q = 0; q < 8; q++) cmax[q] = -3.402823466e38f;
    #pragma unroll
    for (int r = 0; r < 8; r++) {
        if (ty * 8 + r < nv) {
            float f0, f1;
            asm("mov.b64 {%0,%1},%2;" : "=f"(f0), "=f"(f1) : "l"(acc[r * 4 + 0]));
            cmax[0] = fmaxf(cmax[0], f0); cmax[1] = fmaxf(cmax[1], f1);
            asm("mov.b64 {%0,%1},%2;" : "=f"(f0), "=f"(f1) : "l"(acc[r * 4 + 1]));
            cmax[2] = fmaxf(cmax[2], f0); cmax[3] = fmaxf(cmax[3], f1);
            asm("mov.b64 {%0,%1},%2;" : "=f"(f0), "=f"(f1) : "l"(acc[r * 4 + 2]));
            cmax[4] = fmaxf(cmax[4], f0); cmax[5] = fmaxf(cmax[5], f1);
            asm("mov.b64 {%0,%1},%2;" : "=f"(f0), "=f"(f1) : "l"(acc[r * 4 + 3]));
            cmax[6] = fmaxf(cmax[6], f0); cmax[7] = fmaxf(cmax[7], f1);
        }
    }
    __syncthreads();   // all H reads done before overlay
    ((float4*)(RED + ty * 256 + tx * 4))[0]       = make_float4(cmax[0], cmax[1], cmax[2], cmax[3]);
    ((float4*)(RED + ty * 256 + 128 + tx * 4))[0] = make_float4(cmax[4], cmax[5], cmax[6], cmax[7]);
    __syncthreads();
    {
        int col = tid;
        float v = RED[col];
        #pragma unroll
        for (int t = 1; t < 8; t++) v = fmaxf(v, RED[t * 256 + col]);
        out[(long long)m * COUT + col] = v + b2[col];   // nv >= 1 (center itself)
    }
}

// ---------------------------------------------------------------------------
// Kernel 3: auxiliary tuple outputs (pos_dst, batch_dst, lframes_dst)
// ---------------------------------------------------------------------------
__global__ void extras_kernel(const float* __restrict__ pos, const int* __restrict__ batch,
                              const float* __restrict__ lframes, float* __restrict__ out)
{
    int m = blockIdx.x * blockDim.x + threadIdx.x;
    if (m >= Mc) return;
    int c = m * CSTRIDE;
    long long o = (long long)Mc * COUT;
    out[o + m * 3 + 0] = pos[c * 3 + 0];
    out[o + m * 3 + 1] = pos[c * 3 + 1];
    out[o + m * 3 + 2] = pos[c * 3 + 2];
    o += (long long)Mc * 3;
    out[o + m] = (float)batch[c];
    o += Mc;
    #pragma unroll
    for (int j = 0; j < 9; j++) out[o + m * 9 + j] = lframes[c * 9 + j];
}

// ---------------------------------------------------------------------------
extern "C" void kernel_launch(void* const* d_in, const int* in_sizes, int n_in,
                              void* d_out, int out_size)
{
    const float* x       = (const float*)d_in[0];
    const float* pos     = (const float*)d_in[1];
    const int*   batch   = (const int*)  d_in[2];
    const float* lframes = (const float*)d_in[3];
    const float* W1      = (const float*)d_in[4];
    const float* b1      = (const float*)d_in[5];
    const float* W2      = (const float*)d_in[6];
    const float* b2      = (const float*)d_in[7];
    float* out = (float*)d_out;

    float* P_buf; cudaGetSymbolAddress((void**)&P_buf, g_P);
    float* D_buf; cudaGetSymbolAddress((void**)&D_buf, g_D);

    int smem_bytes = (Kn * HID + HID + 3 * HID + 16) * (int)sizeof(float);
    cudaFuncSetAttribute(edge_mlp_kernel,
                         cudaFuncAttributeMaxDynamicSharedMemorySize, smem_bytes);

    ball_query_kernel<<<Mc, 256>>>(pos);
    pre_gemm_kernel<<<Npts / 64, 256>>>(x, W1, nullptr, P_buf, 1);            // P = x @ W1a
    pre_gemm_kernel<<<Mc / 64, 256>>>(x, W1 + CIN * HID, b1, D_buf, CSTRIDE); // D = x_dst @ W1b + b1
    edge_mlp_kernel<<<Mc, 256, smem_bytes>>>(pos, lframes, W1, W2, b2, out);

    long long full = (long long)Mc * COUT + (long long)Mc * 13;
    if ((long long)out_size >= full)
        extras_kernel<<<(Mc + 255) / 256, 256>>>(pos, batch, lframes, out);
}